// round 15
// baseline (speedup 1.0000x reference)
#include <cuda_runtime.h>
#include <math.h>

// ----------------------------------------------------------------------------
// pGNN on GB300: CSR-pull formulation, no feature atomics.
// Pipeline per launch (all graph-capturable kernel launches):
//   detect -> zero -> degree -> scan(+deg_inv_sqrt) -> csr_fill
//   -> gemm1(relu) -> [passA -> passB] x2 -> gemm2+log_softmax
// ----------------------------------------------------------------------------

#define N_MAX   100000
#define E_MAX   1600000
#define HID     64
#define IN_DIM  256
#define OUT_DIM 40

// ---- scratch (module-load allocated; no runtime allocation) ----
__device__ int   g_is64;
__device__ int   g_deg[N_MAX];
__device__ int   g_cursor[N_MAX];
__device__ int   g_rowptr[N_MAX + 1];
__device__ int   g_src[E_MAX];           // CSR: source node per incoming edge
__device__ float g_dis[N_MAX];           // deg^{-1/2} (0 if deg==0)
__device__ float g_alpha[N_MAX];
__device__ float g_beta[N_MAX];
__device__ float g_M[E_MAX];             // per-edge M, CSR order
__device__ float g_h [(size_t)N_MAX * HID];
__device__ float g_o1[(size_t)N_MAX * HID];
__device__ float g_o2[(size_t)N_MAX * HID];

// ---- edge-index access: handles int64 or (JAX x64-off) int32 storage ----
__device__ __forceinline__ int load_idx(const void* ei, long long idx) {
    if (g_is64) return (int)((const long long*)ei)[idx];
    return ((const int*)ei)[idx];
}

// Detect element width: int32 data reinterpreted as int64 yields values with a
// nonzero hi word (>= 2^32) unless the neighboring index is 0 (p ~ 1e-5 each).
__global__ void detect_k(const void* ei, int n) {
    if (blockIdx.x == 0 && threadIdx.x == 0) {
        const long long* p = (const long long*)ei;
        int ok = 1;
        #pragma unroll
        for (int i = 0; i < 16; i++) {
            long long v = p[i];
            if (v < 0 || v >= (long long)n) { ok = 0; break; }
        }
        g_is64 = ok;
    }
}

__global__ void zero_k(int n) {
    int i = blockIdx.x * blockDim.x + threadIdx.x;
    if (i < n) { g_deg[i] = 0; g_cursor[i] = 0; }
}

__global__ void deg_k(const void* ei, int e) {
    int i = blockIdx.x * blockDim.x + threadIdx.x;
    if (i < e) {
        int c = load_idx(ei, (long long)e + i);   // col = edge_index[1]
        atomicAdd(&g_deg[c], 1);
    }
}

// Single-block exclusive scan over degrees -> rowptr, plus deg_inv_sqrt.
__global__ void scan_k(int n) {
    const int T = 1024;
    int t = threadIdx.x;
    int chunk = (n + T - 1) / T;
    int start = t * chunk;
    int end   = min(start + chunk, n);

    int s = 0;
    for (int i = start; i < end; i++) s += g_deg[i];

    __shared__ int sh[T];
    sh[t] = s;
    __syncthreads();
    for (int off = 1; off < T; off <<= 1) {
        int v = (t >= off) ? sh[t - off] : 0;
        __syncthreads();
        sh[t] += v;
        __syncthreads();
    }
    int run = sh[t] - s;   // exclusive prefix of this thread's chunk
    for (int i = start; i < end; i++) {
        int d = g_deg[i];
        g_rowptr[i] = run;
        run += d;
        g_dis[i] = (d > 0) ? rsqrtf((float)d) : 0.0f;
    }
    if (t == T - 1) g_rowptr[n] = sh[T - 1];
}

__global__ void fill_k(const void* ei, int e) {
    int i = blockIdx.x * blockDim.x + threadIdx.x;
    if (i < e) {
        int r = load_idx(ei, i);                  // row = edge_index[0]
        int c = load_idx(ei, (long long)e + i);   // col
        int p = atomicAdd(&g_cursor[c], 1);
        g_src[g_rowptr[c] + p] = r;
    }
}

// ---- GEMM1: h = relu(x @ W1 + b1), [n,256]@[256,64]. 128x64 block tile. ----
__global__ __launch_bounds__(256) void gemm1_k(
    const float* __restrict__ x, const float* __restrict__ W1,
    const float* __restrict__ b1, int n)
{
    __shared__ float As[16][129];   // [k][m], padded vs bank conflicts
    __shared__ float Bs[16][64];    // [k][c]
    int tid = threadIdx.x;
    int tx = tid & 15;              // col group: cols tx + 16*j
    int ty = tid >> 4;              // row group: rows ty + 16*i
    int blockM = blockIdx.x * 128;

    float acc[8][4];
    #pragma unroll
    for (int i = 0; i < 8; i++)
        #pragma unroll
        for (int j = 0; j < 4; j++) acc[i][j] = 0.0f;

    for (int k0 = 0; k0 < IN_DIM; k0 += 16) {
        #pragma unroll
        for (int l = 0; l < 2; l++) {
            int f  = tid + l * 256;          // 512 float4 slots
            int r  = f >> 2;
            int kq = (f & 3) * 4;
            int gr = blockM + r;
            float4 v = (gr < n) ? *(const float4*)(x + (size_t)gr * IN_DIM + k0 + kq)
                                : make_float4(0.f, 0.f, 0.f, 0.f);
            As[kq + 0][r] = v.x; As[kq + 1][r] = v.y;
            As[kq + 2][r] = v.z; As[kq + 3][r] = v.w;
        }
        {
            int kk = tid >> 4;
            int cq = (tid & 15) * 4;
            float4 v = *(const float4*)(W1 + (size_t)(k0 + kk) * HID + cq);
            *(float4*)&Bs[kk][cq] = v;
        }
        __syncthreads();
        #pragma unroll
        for (int k = 0; k < 16; k++) {
            float a[8], b[4];
            #pragma unroll
            for (int i = 0; i < 8; i++) a[i] = As[k][ty + 16 * i];
            #pragma unroll
            for (int j = 0; j < 4; j++) b[j] = Bs[k][tx + 16 * j];
            #pragma unroll
            for (int i = 0; i < 8; i++)
                #pragma unroll
                for (int j = 0; j < 4; j++) acc[i][j] += a[i] * b[j];
        }
        __syncthreads();
    }
    #pragma unroll
    for (int i = 0; i < 8; i++) {
        int gr = blockM + ty + 16 * i;
        if (gr < n) {
            #pragma unroll
            for (int j = 0; j < 4; j++) {
                int c = tx + 16 * j;
                g_h[(size_t)gr * HID + c] = fmaxf(acc[i][j] + b1[c], 0.0f);
            }
        }
    }
}

// ---- pass A: per-edge M = ||d_r*out_r - d_c*out_c||^(P-2), segsum -> alpha/beta
// One warp per destination node; lane l holds features l and l+32.
__global__ void passA_k(int sel, int n) {
    const float* out = sel ? g_o1 : g_h;
    int w    = (blockIdx.x * blockDim.x + threadIdx.x) >> 5;
    int lane = threadIdx.x & 31;
    if (w >= n) return;
    int c = w;
    float dc  = g_dis[c];
    float oc0 = dc * out[(size_t)c * HID + lane];
    float oc1 = dc * out[(size_t)c * HID + lane + 32];
    int beg = g_rowptr[c], end = g_rowptr[c + 1];
    float Msum = 0.0f;
    for (int i = beg; i < end; i++) {
        int   r  = g_src[i];
        float dr = g_dis[r];
        float d0 = dr * out[(size_t)r * HID + lane]      - oc0;
        float d1 = dr * out[(size_t)r * HID + lane + 32] - oc1;
        float s  = d0 * d0 + d1 * d1;
        #pragma unroll
        for (int o = 16; o > 0; o >>= 1) s += __shfl_xor_sync(0xffffffffu, s, o);
        float M = sqrtf(sqrtf(s));            // grad_norm^(P-2) = (s^1/2)^1/2
        if (isinf(M)) M = 0.0f;
        Msum += M;
        if (lane == 0) g_M[i] = M;
    }
    if (lane == 0) {
        float a = 1.0f / (dc * dc * Msum + 0.08f);   // 2*MU/P
        g_alpha[c] = a;
        g_beta[c]  = 0.16f * a;                       // 4*MU/P
    }
}

// ---- pass B: out_new[c] = sum_e alpha[r]*dis[r]*M[e]*dis[c]*out[r] + beta[c]*h[c]
__global__ void passB_k(int sel, int n) {
    const float* in = sel ? g_o1 : g_h;
    float*       nx = sel ? g_o2 : g_o1;
    int w    = (blockIdx.x * blockDim.x + threadIdx.x) >> 5;
    int lane = threadIdx.x & 31;
    if (w >= n) return;
    int c = w;
    float dc = g_dis[c];
    int beg = g_rowptr[c], end = g_rowptr[c + 1];
    float a0 = 0.0f, a1 = 0.0f;
    for (int i = beg; i < end; i++) {
        int   r    = g_src[i];
        float coef = g_alpha[r] * g_dis[r] * g_M[i] * dc;
        a0 += coef * in[(size_t)r * HID + lane];
        a1 += coef * in[(size_t)r * HID + lane + 32];
    }
    float bb = g_beta[c];
    nx[(size_t)c * HID + lane]      = a0 + bb * g_h[(size_t)c * HID + lane];
    nx[(size_t)c * HID + lane + 32] = a1 + bb * g_h[(size_t)c * HID + lane + 32];
}

// ---- GEMM2 + log_softmax fused: logits = o2 @ W2 + b2, lsm over 40 cols ----
// 64 rows per block, 256 threads: 4 threads per row, 10 cols each.
__global__ __launch_bounds__(256) void gemm2_lsm_k(
    const float* __restrict__ W2, const float* __restrict__ b2,
    float* __restrict__ out, int n)
{
    __shared__ float Xs[64][65];
    __shared__ float Ws[64][OUT_DIM];
    __shared__ float b2s[OUT_DIM];
    __shared__ float red[64][4];

    int tid = threadIdx.x;
    int blockM = blockIdx.x * 64;

    for (int idx = tid; idx < 64 * 16; idx += 256) {   // 64 rows x 16 float4
        int r = idx >> 4, kq = (idx & 15) * 4;
        int gr = blockM + r;
        float4 v = (gr < n) ? *(const float4*)(g_o2 + (size_t)gr * HID + kq)
                            : make_float4(0.f, 0.f, 0.f, 0.f);
        Xs[r][kq + 0] = v.x; Xs[r][kq + 1] = v.y;
        Xs[r][kq + 2] = v.z; Xs[r][kq + 3] = v.w;
    }
    for (int idx = tid; idx < 640; idx += 256) {        // 64*40 floats = 640 f4
        int kk = idx / 10, cq = (idx % 10) * 4;
        float4 v = *(const float4*)(W2 + (size_t)kk * OUT_DIM + cq);
        Ws[kk][cq + 0] = v.x; Ws[kk][cq + 1] = v.y;
        Ws[kk][cq + 2] = v.z; Ws[kk][cq + 3] = v.w;
    }
    if (tid < OUT_DIM) b2s[tid] = b2[tid];
    __syncthreads();

    int tRow = tid >> 2;
    int tCol = tid & 3;
    float acc[10];
    #pragma unroll
    for (int j = 0; j < 10; j++) acc[j] = b2s[tCol * 10 + j];
    #pragma unroll 4
    for (int k = 0; k < HID; k++) {
        float xv = Xs[tRow][k];
        #pragma unroll
        for (int j = 0; j < 10; j++) acc[j] += xv * Ws[k][tCol * 10 + j];
    }
    // stable log_softmax across the 4 threads of this row
    float lmax = acc[0];
    #pragma unroll
    for (int j = 1; j < 10; j++) lmax = fmaxf(lmax, acc[j]);
    red[tRow][tCol] = lmax;
    __syncthreads();
    float rmax = fmaxf(fmaxf(red[tRow][0], red[tRow][1]),
                       fmaxf(red[tRow][2], red[tRow][3]));
    __syncthreads();
    float lsum = 0.0f;
    #pragma unroll
    for (int j = 0; j < 10; j++) lsum += expf(acc[j] - rmax);
    red[tRow][tCol] = lsum;
    __syncthreads();
    float rsum = red[tRow][0] + red[tRow][1] + red[tRow][2] + red[tRow][3];
    float lse  = rmax + logf(rsum);

    int gr = blockM + tRow;
    if (gr < n) {
        #pragma unroll
        for (int j = 0; j < 10; j++)
            out[(size_t)gr * OUT_DIM + tCol * 10 + j] = acc[j] - lse;
    }
}

// ----------------------------------------------------------------------------
extern "C" void kernel_launch(void* const* d_in, const int* in_sizes, int n_in,
                              void* d_out, int out_size) {
    const float* x  = (const float*)d_in[0];
    const void*  ei = d_in[1];
    const float* W1 = (const float*)d_in[2];
    const float* b1 = (const float*)d_in[3];
    const float* W2 = (const float*)d_in[4];
    const float* b2 = (const float*)d_in[5];
    float* out = (float*)d_out;

    int n = in_sizes[0] / IN_DIM;   // 100000
    int e = in_sizes[1] / 2;        // 1600000 (element count, dtype-independent)
    if (n > N_MAX) n = N_MAX;
    if (e > E_MAX) e = E_MAX;

    int gN   = (n + 255) / 256;
    int gE   = (e + 255) / 256;
    int gW   = (n + 7) / 8;          // warp-per-node kernels, 256 thr = 8 warps
    int gM1  = (n + 127) / 128;
    int gM2  = (n + 63) / 64;

    detect_k<<<1, 32>>>(ei, n);
    zero_k  <<<gN, 256>>>(n);
    deg_k   <<<gE, 256>>>(ei, e);
    scan_k  <<<1, 1024>>>(n);
    fill_k  <<<gE, 256>>>(ei, e);
    gemm1_k <<<gM1, 256>>>(x, W1, b1, n);

    // K = 2 propagation rounds
    passA_k <<<gW, 256>>>(0, n);   // reads h,  writes M, alpha, beta
    passB_k <<<gW, 256>>>(0, n);   // h  -> o1
    passA_k <<<gW, 256>>>(1, n);   // reads o1
    passB_k <<<gW, 256>>>(1, n);   // o1 -> o2

    gemm2_lsm_k<<<gM2, 256>>>(W2, b2, out, n);
}

// round 16
// speedup vs baseline: 1.0022x; 1.0022x over previous
#include <cuda_runtime.h>
#include <math.h>

// ----------------------------------------------------------------------------
// pGNN on GB300: CSR-pull formulation, no feature atomics.
// Pipeline per launch (all graph-capturable kernel launches):
//   detect -> zero -> degree -> scan(+deg_inv_sqrt) -> csr_fill
//   -> gemm1(relu) -> [passA -> passB] x2 -> gemm2+log_softmax
// ----------------------------------------------------------------------------

#define N_MAX   100000
#define E_MAX   1600000
#define HID     64
#define IN_DIM  256
#define OUT_DIM 40

// ---- scratch (module-load allocated; no runtime allocation) ----
__device__ int   g_is64;
__device__ int   g_deg[N_MAX];
__device__ int   g_cursor[N_MAX];
__device__ int   g_rowptr[N_MAX + 1];
__device__ int   g_src[E_MAX];           // CSR: source node per incoming edge
__device__ float g_dis[N_MAX];           // deg^{-1/2} (0 if deg==0)
__device__ float g_alpha[N_MAX];
__device__ float g_beta[N_MAX];
__device__ float g_M[E_MAX];             // per-edge M, CSR order
__device__ float g_h [(size_t)N_MAX * HID];
__device__ float g_o1[(size_t)N_MAX * HID];
__device__ float g_o2[(size_t)N_MAX * HID];

// ---- edge-index access: handles int64 or (JAX x64-off) int32 storage ----
__device__ __forceinline__ int load_idx(const void* ei, long long idx) {
    if (g_is64) return (int)((const long long*)ei)[idx];
    return ((const int*)ei)[idx];
}

// Detect element width: int32 data reinterpreted as int64 yields values with a
// nonzero hi word (>= 2^32) unless the neighboring index is 0 (p ~ 1e-5 each).
__global__ void detect_k(const void* ei, int n) {
    if (blockIdx.x == 0 && threadIdx.x == 0) {
        const long long* p = (const long long*)ei;
        int ok = 1;
        #pragma unroll
        for (int i = 0; i < 16; i++) {
            long long v = p[i];
            if (v < 0 || v >= (long long)n) { ok = 0; break; }
        }
        g_is64 = ok;
    }
}

__global__ void zero_k(int n) {
    int i = blockIdx.x * blockDim.x + threadIdx.x;
    if (i < n) { g_deg[i] = 0; g_cursor[i] = 0; }
}

__global__ void deg_k(const void* ei, int e) {
    int i = blockIdx.x * blockDim.x + threadIdx.x;
    if (i < e) {
        int c = load_idx(ei, (long long)e + i);   // col = edge_index[1]
        atomicAdd(&g_deg[c], 1);
    }
}

// Single-block exclusive scan over degrees -> rowptr, plus deg_inv_sqrt.
__global__ void scan_k(int n) {
    const int T = 1024;
    int t = threadIdx.x;
    int chunk = (n + T - 1) / T;
    int start = t * chunk;
    int end   = min(start + chunk, n);

    int s = 0;
    for (int i = start; i < end; i++) s += g_deg[i];

    __shared__ int sh[T];
    sh[t] = s;
    __syncthreads();
    for (int off = 1; off < T; off <<= 1) {
        int v = (t >= off) ? sh[t - off] : 0;
        __syncthreads();
        sh[t] += v;
        __syncthreads();
    }
    int run = sh[t] - s;   // exclusive prefix of this thread's chunk
    for (int i = start; i < end; i++) {
        int d = g_deg[i];
        g_rowptr[i] = run;
        run += d;
        g_dis[i] = (d > 0) ? rsqrtf((float)d) : 0.0f;
    }
    if (t == T - 1) g_rowptr[n] = sh[T - 1];
}

__global__ void fill_k(const void* ei, int e) {
    int i = blockIdx.x * blockDim.x + threadIdx.x;
    if (i < e) {
        int r = load_idx(ei, i);                  // row = edge_index[0]
        int c = load_idx(ei, (long long)e + i);   // col
        int p = atomicAdd(&g_cursor[c], 1);
        g_src[g_rowptr[c] + p] = r;
    }
}

// ---- GEMM1: h = relu(x @ W1 + b1), [n,256]@[256,64]. 128x64 block tile. ----
__global__ __launch_bounds__(256) void gemm1_k(
    const float* __restrict__ x, const float* __restrict__ W1,
    const float* __restrict__ b1, int n)
{
    __shared__ float As[16][129];   // [k][m], padded vs bank conflicts
    __shared__ float Bs[16][64];    // [k][c]
    int tid = threadIdx.x;
    int tx = tid & 15;              // col group: cols tx + 16*j
    int ty = tid >> 4;              // row group: rows ty + 16*i
    int blockM = blockIdx.x * 128;

    float acc[8][4];
    #pragma unroll
    for (int i = 0; i < 8; i++)
        #pragma unroll
        for (int j = 0; j < 4; j++) acc[i][j] = 0.0f;

    for (int k0 = 0; k0 < IN_DIM; k0 += 16) {
        #pragma unroll
        for (int l = 0; l < 2; l++) {
            int f  = tid + l * 256;          // 512 float4 slots
            int r  = f >> 2;
            int kq = (f & 3) * 4;
            int gr = blockM + r;
            float4 v = (gr < n) ? *(const float4*)(x + (size_t)gr * IN_DIM + k0 + kq)
                                : make_float4(0.f, 0.f, 0.f, 0.f);
            As[kq + 0][r] = v.x; As[kq + 1][r] = v.y;
            As[kq + 2][r] = v.z; As[kq + 3][r] = v.w;
        }
        {
            int kk = tid >> 4;
            int cq = (tid & 15) * 4;
            float4 v = *(const float4*)(W1 + (size_t)(k0 + kk) * HID + cq);
            *(float4*)&Bs[kk][cq] = v;
        }
        __syncthreads();
        #pragma unroll
        for (int k = 0; k < 16; k++) {
            float a[8], b[4];
            #pragma unroll
            for (int i = 0; i < 8; i++) a[i] = As[k][ty + 16 * i];
            #pragma unroll
            for (int j = 0; j < 4; j++) b[j] = Bs[k][tx + 16 * j];
            #pragma unroll
            for (int i = 0; i < 8; i++)
                #pragma unroll
                for (int j = 0; j < 4; j++) acc[i][j] += a[i] * b[j];
        }
        __syncthreads();
    }
    #pragma unroll
    for (int i = 0; i < 8; i++) {
        int gr = blockM + ty + 16 * i;
        if (gr < n) {
            #pragma unroll
            for (int j = 0; j < 4; j++) {
                int c = tx + 16 * j;
                g_h[(size_t)gr * HID + c] = fmaxf(acc[i][j] + b1[c], 0.0f);
            }
        }
    }
}

// ---- pass A: per-edge M = ||d_r*out_r - d_c*out_c||^(P-2), segsum -> alpha/beta
// One warp per destination node; lane l holds features l and l+32.
__global__ void passA_k(int sel, int n) {
    const float* out = sel ? g_o1 : g_h;
    int w    = (blockIdx.x * blockDim.x + threadIdx.x) >> 5;
    int lane = threadIdx.x & 31;
    if (w >= n) return;
    int c = w;
    float dc  = g_dis[c];
    float oc0 = dc * out[(size_t)c * HID + lane];
    float oc1 = dc * out[(size_t)c * HID + lane + 32];
    int beg = g_rowptr[c], end = g_rowptr[c + 1];
    float Msum = 0.0f;
    for (int i = beg; i < end; i++) {
        int   r  = g_src[i];
        float dr = g_dis[r];
        float d0 = dr * out[(size_t)r * HID + lane]      - oc0;
        float d1 = dr * out[(size_t)r * HID + lane + 32] - oc1;
        float s  = d0 * d0 + d1 * d1;
        #pragma unroll
        for (int o = 16; o > 0; o >>= 1) s += __shfl_xor_sync(0xffffffffu, s, o);
        float M = sqrtf(sqrtf(s));            // grad_norm^(P-2) = (s^1/2)^1/2
        if (isinf(M)) M = 0.0f;
        Msum += M;
        if (lane == 0) g_M[i] = M;
    }
    if (lane == 0) {
        float a = 1.0f / (dc * dc * Msum + 0.08f);   // 2*MU/P
        g_alpha[c] = a;
        g_beta[c]  = 0.16f * a;                       // 4*MU/P
    }
}

// ---- pass B: out_new[c] = sum_e alpha[r]*dis[r]*M[e]*dis[c]*out[r] + beta[c]*h[c]
__global__ void passB_k(int sel, int n) {
    const float* in = sel ? g_o1 : g_h;
    float*       nx = sel ? g_o2 : g_o1;
    int w    = (blockIdx.x * blockDim.x + threadIdx.x) >> 5;
    int lane = threadIdx.x & 31;
    if (w >= n) return;
    int c = w;
    float dc = g_dis[c];
    int beg = g_rowptr[c], end = g_rowptr[c + 1];
    float a0 = 0.0f, a1 = 0.0f;
    for (int i = beg; i < end; i++) {
        int   r    = g_src[i];
        float coef = g_alpha[r] * g_dis[r] * g_M[i] * dc;
        a0 += coef * in[(size_t)r * HID + lane];
        a1 += coef * in[(size_t)r * HID + lane + 32];
    }
    float bb = g_beta[c];
    nx[(size_t)c * HID + lane]      = a0 + bb * g_h[(size_t)c * HID + lane];
    nx[(size_t)c * HID + lane + 32] = a1 + bb * g_h[(size_t)c * HID + lane + 32];
}

// ---- GEMM2 + log_softmax fused: logits = o2 @ W2 + b2, lsm over 40 cols ----
// 64 rows per block, 256 threads: 4 threads per row, 10 cols each.
__global__ __launch_bounds__(256) void gemm2_lsm_k(
    const float* __restrict__ W2, const float* __restrict__ b2,
    float* __restrict__ out, int n)
{
    __shared__ float Xs[64][65];
    __shared__ float Ws[64][OUT_DIM];
    __shared__ float b2s[OUT_DIM];
    __shared__ float red[64][4];

    int tid = threadIdx.x;
    int blockM = blockIdx.x * 64;

    for (int idx = tid; idx < 64 * 16; idx += 256) {   // 64 rows x 16 float4
        int r = idx >> 4, kq = (idx & 15) * 4;
        int gr = blockM + r;
        float4 v = (gr < n) ? *(const float4*)(g_o2 + (size_t)gr * HID + kq)
                            : make_float4(0.f, 0.f, 0.f, 0.f);
        Xs[r][kq + 0] = v.x; Xs[r][kq + 1] = v.y;
        Xs[r][kq + 2] = v.z; Xs[r][kq + 3] = v.w;
    }
    for (int idx = tid; idx < 640; idx += 256) {        // 64*40 floats = 640 f4
        int kk = idx / 10, cq = (idx % 10) * 4;
        float4 v = *(const float4*)(W2 + (size_t)kk * OUT_DIM + cq);
        Ws[kk][cq + 0] = v.x; Ws[kk][cq + 1] = v.y;
        Ws[kk][cq + 2] = v.z; Ws[kk][cq + 3] = v.w;
    }
    if (tid < OUT_DIM) b2s[tid] = b2[tid];
    __syncthreads();

    int tRow = tid >> 2;
    int tCol = tid & 3;
    float acc[10];
    #pragma unroll
    for (int j = 0; j < 10; j++) acc[j] = b2s[tCol * 10 + j];
    #pragma unroll 4
    for (int k = 0; k < HID; k++) {
        float xv = Xs[tRow][k];
        #pragma unroll
        for (int j = 0; j < 10; j++) acc[j] += xv * Ws[k][tCol * 10 + j];
    }
    // stable log_softmax across the 4 threads of this row
    float lmax = acc[0];
    #pragma unroll
    for (int j = 1; j < 10; j++) lmax = fmaxf(lmax, acc[j]);
    red[tRow][tCol] = lmax;
    __syncthreads();
    float rmax = fmaxf(fmaxf(red[tRow][0], red[tRow][1]),
                       fmaxf(red[tRow][2], red[tRow][3]));
    __syncthreads();
    float lsum = 0.0f;
    #pragma unroll
    for (int j = 0; j < 10; j++) lsum += expf(acc[j] - rmax);
    red[tRow][tCol] = lsum;
    __syncthreads();
    float rsum = red[tRow][0] + red[tRow][1] + red[tRow][2] + red[tRow][3];
    float lse  = rmax + logf(rsum);

    int gr = blockM + tRow;
    if (gr < n) {
        #pragma unroll
        for (int j = 0; j < 10; j++)
            out[(size_t)gr * OUT_DIM + tCol * 10 + j] = acc[j] - lse;
    }
}

// ----------------------------------------------------------------------------
extern "C" void kernel_launch(void* const* d_in, const int* in_sizes, int n_in,
                              void* d_out, int out_size) {
    const float* x  = (const float*)d_in[0];
    const void*  ei = d_in[1];
    const float* W1 = (const float*)d_in[2];
    const float* b1 = (const float*)d_in[3];
    const float* W2 = (const float*)d_in[4];
    const float* b2 = (const float*)d_in[5];
    float* out = (float*)d_out;

    int n = in_sizes[0] / IN_DIM;   // 100000
    int e = in_sizes[1] / 2;        // 1600000 (element count, dtype-independent)
    if (n > N_MAX) n = N_MAX;
    if (e > E_MAX) e = E_MAX;

    int gN   = (n + 255) / 256;
    int gE   = (e + 255) / 256;
    int gW   = (n + 7) / 8;          // warp-per-node kernels, 256 thr = 8 warps
    int gM1  = (n + 127) / 128;
    int gM2  = (n + 63) / 64;

    detect_k<<<1, 32>>>(ei, n);
    zero_k  <<<gN, 256>>>(n);
    deg_k   <<<gE, 256>>>(ei, e);
    scan_k  <<<1, 1024>>>(n);
    fill_k  <<<gE, 256>>>(ei, e);
    gemm1_k <<<gM1, 256>>>(x, W1, b1, n);

    // K = 2 propagation rounds
    passA_k <<<gW, 256>>>(0, n);   // reads h,  writes M, alpha, beta
    passB_k <<<gW, 256>>>(0, n);   // h  -> o1
    passA_k <<<gW, 256>>>(1, n);   // reads o1
    passB_k <<<gW, 256>>>(1, n);   // o1 -> o2

    gemm2_lsm_k<<<gM2, 256>>>(W2, b2, out, n);
}